// round 6
// baseline (speedup 1.0000x reference)
#include <cuda_runtime.h>
#include <cuda_bf16.h>
#include <math.h>

// Problem constants
#define N_TOK   32768
#define C_DIM   768
#define H_HEADS 8
#define K_WIN   256
#define HD_DIM  96
#define P_WIN   (N_TOK / K_WIN)   // 128
#define NQKV    (3 * C_DIM)       // 2304

// ---------------------------------------------------------------------------
// Scratch (static device arrays; no allocation allowed)
// ---------------------------------------------------------------------------
__device__ float g_qkv[(size_t)N_TOK * NQKV];
__device__ float g_q  [(size_t)N_TOK * C_DIM];
__device__ float g_k  [(size_t)N_TOK * C_DIM];
__device__ float g_v  [(size_t)N_TOK * C_DIM];
__device__ float g_att[(size_t)N_TOK * C_DIM];

// bf16 split operands
__device__ __nv_bfloat16 g_Ah [(size_t)N_TOK * C_DIM];
__device__ __nv_bfloat16 g_Al [(size_t)N_TOK * C_DIM];
__device__ __nv_bfloat16 g_A2h[(size_t)N_TOK * C_DIM];
__device__ __nv_bfloat16 g_A2l[(size_t)N_TOK * C_DIM];
__device__ __nv_bfloat16 g_Bqh[(size_t)NQKV * C_DIM];
__device__ __nv_bfloat16 g_Bql[(size_t)NQKV * C_DIM];
__device__ __nv_bfloat16 g_Bph[(size_t)C_DIM * C_DIM];
__device__ __nv_bfloat16 g_Bpl[(size_t)C_DIM * C_DIM];

// ---------------------------------------------------------------------------
// PTX helpers (sm_80-era: mma.sync / ldmatrix / cp.async — legal on sm_103)
// ---------------------------------------------------------------------------
__device__ __forceinline__ unsigned smem_u32(const void* p) {
    unsigned a;
    asm("{ .reg .u64 t; cvta.to.shared.u64 t, %1; cvt.u32.u64 %0, t; }" : "=r"(a) : "l"(p));
    return a;
}

__device__ __forceinline__ void cp16(unsigned saddr, const void* g) {
    asm volatile("cp.async.cg.shared.global [%0], [%1], 16;" :: "r"(saddr), "l"(g));
}
#define CP_COMMIT()  asm volatile("cp.async.commit_group;" ::: "memory")
#define CP_WAIT(n)   asm volatile("cp.async.wait_group %0;" :: "n"(n) : "memory")

__device__ __forceinline__ void ldsm4(unsigned r[4], unsigned addr) {
    asm volatile("ldmatrix.sync.aligned.m8n8.x4.shared.b16 {%0,%1,%2,%3}, [%4];"
                 : "=r"(r[0]), "=r"(r[1]), "=r"(r[2]), "=r"(r[3]) : "r"(addr));
}

__device__ __forceinline__ void mma_bf16(float d[4], const unsigned a[4],
                                         const unsigned* b) {
    asm volatile(
        "mma.sync.aligned.m16n8k16.row.col.f32.bf16.bf16.f32 "
        "{%0,%1,%2,%3}, {%4,%5,%6,%7}, {%8,%9}, {%0,%1,%2,%3};"
        : "+f"(d[0]), "+f"(d[1]), "+f"(d[2]), "+f"(d[3])
        : "r"(a[0]), "r"(a[1]), "r"(a[2]), "r"(a[3]), "r"(b[0]), "r"(b[1]));
}

// ---------------------------------------------------------------------------
// fp32 -> bf16 hi/lo split (flat)
// ---------------------------------------------------------------------------
__global__ __launch_bounds__(256) void conv_split(
    const float* __restrict__ X, __nv_bfloat16* __restrict__ hi,
    __nv_bfloat16* __restrict__ lo, int n4)
{
    int i = blockIdx.x * 256 + threadIdx.x;
    if (i >= n4) return;
    float4 v = ((const float4*)X)[i];
    __nv_bfloat16 h0 = __float2bfloat16(v.x), h1 = __float2bfloat16(v.y);
    __nv_bfloat16 h2 = __float2bfloat16(v.z), h3 = __float2bfloat16(v.w);
    __nv_bfloat16 l0 = __float2bfloat16(v.x - __bfloat162float(h0));
    __nv_bfloat16 l1 = __float2bfloat16(v.y - __bfloat162float(h1));
    __nv_bfloat16 l2 = __float2bfloat16(v.z - __bfloat162float(h2));
    __nv_bfloat16 l3 = __float2bfloat16(v.w - __bfloat162float(h3));
    __nv_bfloat162 hp0 = {h0, h1}, hp1 = {h2, h3};
    __nv_bfloat162 lp0 = {l0, l1}, lp1 = {l2, l3};
    uint2 hv, lv;
    hv.x = *(unsigned*)&hp0; hv.y = *(unsigned*)&hp1;
    lv.x = *(unsigned*)&lp0; lv.y = *(unsigned*)&lp1;
    ((uint2*)hi)[i] = hv;
    ((uint2*)lo)[i] = lv;
}

// ---------------------------------------------------------------------------
// Weight transpose + split: W[K,N] (N contiguous) -> hiT/loT [N,K] (K contiguous)
// ---------------------------------------------------------------------------
__global__ __launch_bounds__(256) void conv_split_T(
    const float* __restrict__ W, __nv_bfloat16* __restrict__ hiT,
    __nv_bfloat16* __restrict__ loT, int Kdim, int Ndim)
{
    __shared__ float t[32][33];
    const int n0 = blockIdx.x * 32, k0 = blockIdx.y * 32;
    const int tx = threadIdx.x, ty = threadIdx.y;
#pragma unroll
    for (int d = 0; d < 32; d += 8)
        t[ty + d][tx] = W[(size_t)(k0 + ty + d) * Ndim + n0 + tx];
    __syncthreads();
#pragma unroll
    for (int d = 0; d < 32; d += 8) {
        float v = t[tx][ty + d];
        __nv_bfloat16 h = __float2bfloat16(v);
        __nv_bfloat16 l = __float2bfloat16(v - __bfloat162float(h));
        size_t o = (size_t)(n0 + ty + d) * Kdim + k0 + tx;
        hiT[o] = h;
        loT[o] = l;
    }
}

// ---------------------------------------------------------------------------
// Row-gathered split: row i <- X[map[i], :]
// ---------------------------------------------------------------------------
__global__ __launch_bounds__(192) void conv_split_gather(
    const float* __restrict__ X, const int* __restrict__ map,
    __nv_bfloat16* __restrict__ hi, __nv_bfloat16* __restrict__ lo)
{
    const int row = blockIdx.x;
    const int src = map[row];
    const float4* xs = (const float4*)(X + (size_t)src * C_DIM);
    const int j = threadIdx.x;   // 192 threads, C_DIM/4 = 192
    float4 v = xs[j];
    __nv_bfloat16 h0 = __float2bfloat16(v.x), h1 = __float2bfloat16(v.y);
    __nv_bfloat16 h2 = __float2bfloat16(v.z), h3 = __float2bfloat16(v.w);
    __nv_bfloat16 l0 = __float2bfloat16(v.x - __bfloat162float(h0));
    __nv_bfloat16 l1 = __float2bfloat16(v.y - __bfloat162float(h1));
    __nv_bfloat16 l2 = __float2bfloat16(v.z - __bfloat162float(h2));
    __nv_bfloat16 l3 = __float2bfloat16(v.w - __bfloat162float(h3));
    __nv_bfloat162 hp0 = {h0, h1}, hp1 = {h2, h3};
    __nv_bfloat162 lp0 = {l0, l1}, lp1 = {l2, l3};
    uint2 hv, lv;
    hv.x = *(unsigned*)&hp0; hv.y = *(unsigned*)&hp1;
    lv.x = *(unsigned*)&lp0; lv.y = *(unsigned*)&lp1;
    ((uint2*)(hi + (size_t)row * C_DIM))[j] = hv;
    ((uint2*)(lo + (size_t)row * C_DIM))[j] = lv;
}

// ---------------------------------------------------------------------------
// HMMA split-bf16 GEMM: C[M,N] = A@B^T + bias.  A=[M,K] hi/lo, B=[N,K] hi/lo.
// CTA tile 128x128, BK=32, 8 warps (4M x 2N), warp tile 32x64, m16n8k16.
// 2-stage cp.async pipeline. smem rows padded to 80B for conflict-free ldmatrix.
// ---------------------------------------------------------------------------
#define TS        80                       // smem row stride bytes (32 bf16 + pad)
#define TILE_SZ   (128 * TS)               // 10240
#define OFF_AH    0
#define OFF_AL    TILE_SZ
#define OFF_BH    (2 * TILE_SZ)
#define OFF_BL    (3 * TILE_SZ)
#define STAGE_SZ  (4 * TILE_SZ)            // 40960
#define SMEM_GEMM (2 * STAGE_SZ)           // 81920

__global__ __launch_bounds__(256) void mma_gemm(
    const __nv_bfloat16* __restrict__ Ah, const __nv_bfloat16* __restrict__ Al,
    const __nv_bfloat16* __restrict__ Bh, const __nv_bfloat16* __restrict__ Bl,
    const float* __restrict__ bias, float* __restrict__ C, int Kdim, int Ndim)
{
    extern __shared__ char smem[];
    const unsigned sbase = smem_u32(smem);
    const int tid  = threadIdx.x;
    const int lane = tid & 31;
    const int wid  = tid >> 5;
    const int wm   = wid & 3;        // 0..3 -> M offset wm*32
    const int wn   = wid >> 2;       // 0..1 -> N offset wn*64
    const int bx = blockIdx.x, by = blockIdx.y;

    // gmem load mapping: per array, thread handles idx = tid, tid+256
    // idx -> row = idx/4, c16 = idx%4 (16B chunks of a 64B row)
    const int r0 = tid >> 2, c0 = (tid & 3);

    // ldmatrix lane address components
    const unsigned a_lane = (lane & 15) * TS + (lane >> 4) * 16;
    const unsigned b_lane = ((lane & 7) + ((lane >> 4) & 1) * 8) * TS +
                            ((lane >> 3) & 1) * 16;

    float acc[2][8][4];
#pragma unroll
    for (int mi = 0; mi < 2; mi++)
#pragma unroll
        for (int ni = 0; ni < 8; ni++)
#pragma unroll
            for (int c = 0; c < 4; c++) acc[mi][ni][c] = 0.0f;

    const int nch = Kdim >> 5;   // K chunks of 32

    // ---- stage loader (cp.async) ----
    auto load_stage = [&](int ch, int stage) {
        const int kt = ch << 5;
        const unsigned sb = sbase + stage * STAGE_SZ;
#pragma unroll
        for (int i = 0; i < 2; i++) {
            const int row = r0 + i * 64;
            const int c16 = c0;
            const unsigned so = row * TS + c16 * 16;
            const size_t ga = (size_t)(by * 128 + row) * Kdim + kt + c16 * 8;
            const size_t gb = (size_t)(bx * 128 + row) * Kdim + kt + c16 * 8;
            cp16(sb + OFF_AH + so, Ah + ga);
            cp16(sb + OFF_AL + so, Al + ga);
            cp16(sb + OFF_BH + so, Bh + gb);
            cp16(sb + OFF_BL + so, Bl + gb);
        }
        CP_COMMIT();
    };

    load_stage(0, 0);

    for (int ch = 0; ch < nch; ch++) {
        if (ch + 1 < nch) {
            load_stage(ch + 1, (ch + 1) & 1);
            CP_WAIT(1);
        } else {
            CP_WAIT(0);
        }
        __syncthreads();

        const unsigned sb = sbase + (ch & 1) * STAGE_SZ;
        const unsigned aH = sb + OFF_AH + (wm * 32) * TS + a_lane;
        const unsigned aL = sb + OFF_AL + (wm * 32) * TS + a_lane;
        const unsigned bH = sb + OFF_BH + (wn * 64) * TS + b_lane;
        const unsigned bL = sb + OFF_BL + (wn * 64) * TS + b_lane;

#pragma unroll
        for (int ks = 0; ks < 2; ks++) {
            unsigned ah[2][4], al[2][4], bh[4][4], bl[4][4];
#pragma unroll
            for (int mi = 0; mi < 2; mi++) {
                ldsm4(ah[mi], aH + mi * (16 * TS) + ks * 32);
                ldsm4(al[mi], aL + mi * (16 * TS) + ks * 32);
            }
#pragma unroll
            for (int nj = 0; nj < 4; nj++) {
                ldsm4(bh[nj], bH + nj * (16 * TS) + ks * 32);
                ldsm4(bl[nj], bL + nj * (16 * TS) + ks * 32);
            }
#pragma unroll
            for (int mi = 0; mi < 2; mi++)
#pragma unroll
                for (int nj = 0; nj < 4; nj++)
#pragma unroll
                    for (int hf = 0; hf < 2; hf++) {
                        const int ni = nj * 2 + hf;
                        mma_bf16(acc[mi][ni], ah[mi], &bh[nj][hf * 2]);  // h*h
                        mma_bf16(acc[mi][ni], ah[mi], &bl[nj][hf * 2]);  // h*l
                        mma_bf16(acc[mi][ni], al[mi], &bh[nj][hf * 2]);  // l*h
                    }
        }
        __syncthreads();
    }

    // ---- epilogue: bias + store fp32 ----
#pragma unroll
    for (int ni = 0; ni < 8; ni++) {
        const int col = bx * 128 + wn * 64 + ni * 8 + (lane & 3) * 2;
        const float2 bb = *(const float2*)(bias + col);
#pragma unroll
        for (int mi = 0; mi < 2; mi++) {
            const int row = by * 128 + wm * 32 + mi * 16 + (lane >> 2);
            float2 v0, v1;
            v0.x = acc[mi][ni][0] + bb.x;
            v0.y = acc[mi][ni][1] + bb.y;
            v1.x = acc[mi][ni][2] + bb.x;
            v1.y = acc[mi][ni][3] + bb.y;
            *(float2*)(C + (size_t)row * Ndim + col) = v0;
            *(float2*)(C + (size_t)(row + 8) * Ndim + col) = v1;
        }
    }
}

// ---------------------------------------------------------------------------
// Gather by `order` + 3-axis RoPE on q,k; straight copy for v.  (fp32)
// ---------------------------------------------------------------------------
__global__ __launch_bounds__(384) void gather_rope_kernel(
    const int* __restrict__ order, const int* __restrict__ grid_coord)
{
    const int n = blockIdx.x;
    const int tid = threadIdx.x;
    const int src = order[n];

    const float* qkv = g_qkv + (size_t)src * NQKV;
    float* qo = g_q + (size_t)n * C_DIM;
    float* ko = g_k + (size_t)n * C_DIM;
    float* vo = g_v + (size_t)n * C_DIM;

    for (int j = tid; j < C_DIM; j += 384)
        vo[j] = qkv[2 * C_DIM + j];

    const int h = tid / 48;
    const int rem = tid % 48;
    const int a = rem / 16;
    const int i = rem & 15;

    const float pos = (float)grid_coord[src * 3 + a];
    const float invf = exp2f(-(float)i * 0.4152410118609212f);
    const float ang = pos * invf;
    float s, c;
    sincosf(ang, &s, &c);

    const int base = h * 96 + a * 32 + i;
    {
        float x1 = qkv[base];
        float x2 = qkv[base + 16];
        qo[base]      = x1 * c - x2 * s;
        qo[base + 16] = x1 * s + x2 * c;
    }
    {
        float x1 = qkv[C_DIM + base];
        float x2 = qkv[C_DIM + base + 16];
        ko[base]      = x1 * c - x2 * s;
        ko[base + 16] = x1 * s + x2 * c;
    }
}

// ---------------------------------------------------------------------------
// Packed fp32x2 helpers for attention
// ---------------------------------------------------------------------------
__device__ __forceinline__ unsigned long long dup2(float x) {
    unsigned long long r;
    asm("mov.b64 %0, {%1, %1};" : "=l"(r) : "f"(x));
    return r;
}
__device__ __forceinline__ void fma2(unsigned long long& d,
                                     unsigned long long a, unsigned long long b) {
    asm("fma.rn.f32x2 %0, %1, %2, %0;" : "+l"(d) : "l"(a), "l"(b));
}
__device__ __forceinline__ unsigned long long mul2(unsigned long long a,
                                                   unsigned long long b) {
    unsigned long long r;
    asm("mul.rn.f32x2 %0, %1, %2;" : "=l"(r) : "l"(a), "l"(b));
    return r;
}
__device__ __forceinline__ float2 unpk2(unsigned long long v) {
    float2 f;
    asm("mov.b64 {%0, %1}, %2;" : "=f"(f.x), "=f"(f.y) : "l"(v));
    return f;
}

// ---------------------------------------------------------------------------
// Windowed attention: block per (window, head), 256 threads = 1 query/thread.
// ---------------------------------------------------------------------------
__global__ __launch_bounds__(256, 1) void attn_kernel()
{
    extern __shared__ float sm[];
    float* ks = sm;
    float* vs = sm + K_WIN * HD_DIM;

    const int p = blockIdx.x;
    const int h = blockIdx.y;
    const int tid = threadIdx.x;

    const float* kbase = g_k + (size_t)p * K_WIN * C_DIM + h * HD_DIM;
    const float* vbase = g_v + (size_t)p * K_WIN * C_DIM + h * HD_DIM;

    for (int idx = tid; idx < K_WIN * (HD_DIM / 4); idx += 256) {
        const int j  = idx / (HD_DIM / 4);
        const int c4 = idx % (HD_DIM / 4);
        ((float4*)ks)[idx] = *(const float4*)(kbase + (size_t)j * C_DIM + c4 * 4);
        ((float4*)vs)[idx] = *(const float4*)(vbase + (size_t)j * C_DIM + c4 * 4);
    }

    unsigned long long q2[HD_DIM / 2];
    {
        const double2* qrow = (const double2*)(g_q + (size_t)(p * K_WIN + tid) * C_DIM + h * HD_DIM);
#pragma unroll
        for (int c = 0; c < HD_DIM / 4; c++) {
            double2 t = qrow[c];
            q2[2 * c + 0] = __double_as_longlong(t.x);
            q2[2 * c + 1] = __double_as_longlong(t.y);
        }
    }
    __syncthreads();

    const float scale = rsqrtf((float)HD_DIM);

    float m = -1e30f;
    float l = 0.0f;
    unsigned long long o2[HD_DIM / 2];
#pragma unroll
    for (int c = 0; c < HD_DIM / 2; c++) o2[c] = 0ull;

    for (int j = 0; j < K_WIN; j++) {
        const double2* kr = (const double2*)(ks + j * HD_DIM);
        unsigned long long acc[4] = {0ull, 0ull, 0ull, 0ull};
#pragma unroll
        for (int c = 0; c < HD_DIM / 4; c++) {
            double2 t = kr[c];
            fma2(acc[(2 * c) & 3],     q2[2 * c + 0], __double_as_longlong(t.x));
            fma2(acc[(2 * c + 1) & 3], q2[2 * c + 1], __double_as_longlong(t.y));
        }
        float2 r0 = unpk2(acc[0]), r1 = unpk2(acc[1]);
        float2 r2 = unpk2(acc[2]), r3 = unpk2(acc[3]);
        float dot = ((r0.x + r0.y) + (r1.x + r1.y)) + ((r2.x + r2.y) + (r3.x + r3.y));

        float pnum;
        if (dot > m) {
            float corr = __expf((m - dot) * scale);
            unsigned long long corr2 = dup2(corr);
#pragma unroll
            for (int c = 0; c < HD_DIM / 2; c++) o2[c] = mul2(o2[c], corr2);
            l *= corr;
            m = dot;
            pnum = 1.0f;
        } else {
            pnum = __expf((dot - m) * scale);
        }
        l += pnum;

        unsigned long long p2 = dup2(pnum);
        const double2* vr = (const double2*)(vs + j * HD_DIM);
#pragma unroll
        for (int c = 0; c < HD_DIM / 4; c++) {
            double2 t = vr[c];
            fma2(o2[2 * c + 0], p2, __double_as_longlong(t.x));
            fma2(o2[2 * c + 1], p2, __double_as_longlong(t.y));
        }
    }

    const float invl = 1.0f / l;
    float* orow = g_att + (size_t)(p * K_WIN + tid) * C_DIM + h * HD_DIM;
#pragma unroll
    for (int c = 0; c < HD_DIM / 4; c++) {
        float2 a = unpk2(o2[2 * c + 0]);
        float2 b = unpk2(o2[2 * c + 1]);
        float4 ov;
        ov.x = a.x * invl;
        ov.y = a.y * invl;
        ov.z = b.x * invl;
        ov.w = b.y * invl;
        *(float4*)(orow + c * 4) = ov;
    }
}

// ---------------------------------------------------------------------------
// Launch
// ---------------------------------------------------------------------------
extern "C" void kernel_launch(void* const* d_in, const int* in_sizes, int n_in,
                              void* d_out, int out_size)
{
    const float* feat       = (const float*)d_in[0];
    const int*   grid_coord = (const int*)d_in[1];
    const int*   order      = (const int*)d_in[2];
    const int*   inverse    = (const int*)d_in[3];
    const float* w_qkv      = (const float*)d_in[4];
    const float* b_qkv      = (const float*)d_in[5];
    const float* w_proj     = (const float*)d_in[6];
    const float* b_proj     = (const float*)d_in[7];
    float* out = (float*)d_out;

    float *qkv_p = nullptr, *att_p = nullptr;
    cudaGetSymbolAddress((void**)&qkv_p, g_qkv);
    cudaGetSymbolAddress((void**)&att_p, g_att);

    __nv_bfloat16 *Ah, *Al, *A2h, *A2l, *Bqh, *Bql, *Bph, *Bpl;
    cudaGetSymbolAddress((void**)&Ah,  g_Ah);
    cudaGetSymbolAddress((void**)&Al,  g_Al);
    cudaGetSymbolAddress((void**)&A2h, g_A2h);
    cudaGetSymbolAddress((void**)&A2l, g_A2l);
    cudaGetSymbolAddress((void**)&Bqh, g_Bqh);
    cudaGetSymbolAddress((void**)&Bql, g_Bql);
    cudaGetSymbolAddress((void**)&Bph, g_Bph);
    cudaGetSymbolAddress((void**)&Bpl, g_Bpl);

    const int smem_attn = K_WIN * HD_DIM * 2 * sizeof(float);  // 196608 B
    cudaFuncSetAttribute(attn_kernel, cudaFuncAttributeMaxDynamicSharedMemorySize, smem_attn);
    cudaFuncSetAttribute(mma_gemm, cudaFuncAttributeMaxDynamicSharedMemorySize, SMEM_GEMM);

    // 0) operand conversions
    {
        int n4 = N_TOK * C_DIM / 4;
        conv_split<<<(n4 + 255) / 256, 256>>>(feat, Ah, Al, n4);
        conv_split_T<<<dim3(NQKV / 32, C_DIM / 32), dim3(32, 8)>>>(w_qkv, Bqh, Bql, C_DIM, NQKV);
        conv_split_T<<<dim3(C_DIM / 32, C_DIM / 32), dim3(32, 8)>>>(w_proj, Bph, Bpl, C_DIM, C_DIM);
    }

    // 1) qkv = feat @ w_qkv + b_qkv  (HMMA, split bf16)
    mma_gemm<<<dim3(NQKV / 128, N_TOK / 128), 256, SMEM_GEMM>>>(
        Ah, Al, Bqh, Bql, b_qkv, qkv_p, C_DIM, NQKV);

    // 2) gather by order + RoPE
    gather_rope_kernel<<<N_TOK, 384>>>(order, grid_coord);

    // 3) windowed attention
    attn_kernel<<<dim3(P_WIN, H_HEADS), 256, smem_attn>>>();

    // 4) gathered conversion of attention output (fuses `inverse` permute)
    conv_split_gather<<<N_TOK, 192>>>(att_p, inverse, A2h, A2l);

    // 5) out = g_att[inverse] @ w_proj + b_proj
    mma_gemm<<<dim3(C_DIM / 128, N_TOK / 128), 256, SMEM_GEMM>>>(
        A2h, A2l, Bph, Bpl, b_proj, out, C_DIM, C_DIM);
}

// round 7
// speedup vs baseline: 1.0026x; 1.0026x over previous
#include <cuda_runtime.h>
#include <cuda_bf16.h>
#include <math.h>

// Problem constants
#define N_TOK   32768
#define C_DIM   768
#define H_HEADS 8
#define K_WIN   256
#define HD_DIM  96
#define P_WIN   (N_TOK / K_WIN)   // 128
#define NQKV    (3 * C_DIM)       // 2304

// ---------------------------------------------------------------------------
// Scratch (static device arrays; no allocation allowed)
// ---------------------------------------------------------------------------
__device__ float g_qkv[(size_t)N_TOK * NQKV];
__device__ float g_q  [(size_t)N_TOK * C_DIM];
__device__ float g_k  [(size_t)N_TOK * C_DIM];
__device__ float g_v  [(size_t)N_TOK * C_DIM];
__device__ float g_att[(size_t)N_TOK * C_DIM];

// bf16 split operands
__device__ __nv_bfloat16 g_Ah [(size_t)N_TOK * C_DIM];
__device__ __nv_bfloat16 g_Al [(size_t)N_TOK * C_DIM];
__device__ __nv_bfloat16 g_A2h[(size_t)N_TOK * C_DIM];
__device__ __nv_bfloat16 g_A2l[(size_t)N_TOK * C_DIM];
__device__ __nv_bfloat16 g_Bqh[(size_t)NQKV * C_DIM];
__device__ __nv_bfloat16 g_Bql[(size_t)NQKV * C_DIM];
__device__ __nv_bfloat16 g_Bph[(size_t)C_DIM * C_DIM];
__device__ __nv_bfloat16 g_Bpl[(size_t)C_DIM * C_DIM];

// ---------------------------------------------------------------------------
// PTX helpers (sm_80-era: mma.sync / ldmatrix / cp.async — legal on sm_103)
// ---------------------------------------------------------------------------
__device__ __forceinline__ unsigned smem_u32(const void* p) {
    unsigned a;
    asm("{ .reg .u64 t; cvta.to.shared.u64 t, %1; cvt.u32.u64 %0, t; }" : "=r"(a) : "l"(p));
    return a;
}

__device__ __forceinline__ void cp16(unsigned saddr, const void* g) {
    asm volatile("cp.async.cg.shared.global [%0], [%1], 16;" :: "r"(saddr), "l"(g));
}
#define CP_COMMIT()  asm volatile("cp.async.commit_group;" ::: "memory")
#define CP_WAIT(n)   asm volatile("cp.async.wait_group %0;" :: "n"(n) : "memory")

__device__ __forceinline__ void ldsm4(unsigned r[4], unsigned addr) {
    asm volatile("ldmatrix.sync.aligned.m8n8.x4.shared.b16 {%0,%1,%2,%3}, [%4];"
                 : "=r"(r[0]), "=r"(r[1]), "=r"(r[2]), "=r"(r[3]) : "r"(addr));
}

__device__ __forceinline__ void mma_bf16(float d[4], const unsigned a[4],
                                         const unsigned* b) {
    asm volatile(
        "mma.sync.aligned.m16n8k16.row.col.f32.bf16.bf16.f32 "
        "{%0,%1,%2,%3}, {%4,%5,%6,%7}, {%8,%9}, {%0,%1,%2,%3};"
        : "+f"(d[0]), "+f"(d[1]), "+f"(d[2]), "+f"(d[3])
        : "r"(a[0]), "r"(a[1]), "r"(a[2]), "r"(a[3]), "r"(b[0]), "r"(b[1]));
}

// ---------------------------------------------------------------------------
// fp32 -> bf16 hi/lo split (flat)
// ---------------------------------------------------------------------------
__global__ __launch_bounds__(256) void conv_split(
    const float* __restrict__ X, __nv_bfloat16* __restrict__ hi,
    __nv_bfloat16* __restrict__ lo, int n4)
{
    int i = blockIdx.x * 256 + threadIdx.x;
    if (i >= n4) return;
    float4 v = ((const float4*)X)[i];
    __nv_bfloat16 h0 = __float2bfloat16(v.x), h1 = __float2bfloat16(v.y);
    __nv_bfloat16 h2 = __float2bfloat16(v.z), h3 = __float2bfloat16(v.w);
    __nv_bfloat16 l0 = __float2bfloat16(v.x - __bfloat162float(h0));
    __nv_bfloat16 l1 = __float2bfloat16(v.y - __bfloat162float(h1));
    __nv_bfloat16 l2 = __float2bfloat16(v.z - __bfloat162float(h2));
    __nv_bfloat16 l3 = __float2bfloat16(v.w - __bfloat162float(h3));
    __nv_bfloat162 hp0 = {h0, h1}, hp1 = {h2, h3};
    __nv_bfloat162 lp0 = {l0, l1}, lp1 = {l2, l3};
    uint2 hv, lv;
    hv.x = *(unsigned*)&hp0; hv.y = *(unsigned*)&hp1;
    lv.x = *(unsigned*)&lp0; lv.y = *(unsigned*)&lp1;
    ((uint2*)hi)[i] = hv;
    ((uint2*)lo)[i] = lv;
}

// ---------------------------------------------------------------------------
// Weight transpose + split: W[K,N] (N contiguous) -> hiT/loT [N,K] (K contiguous)
// ---------------------------------------------------------------------------
__global__ __launch_bounds__(256) void conv_split_T(
    const float* __restrict__ W, __nv_bfloat16* __restrict__ hiT,
    __nv_bfloat16* __restrict__ loT, int Kdim, int Ndim)
{
    __shared__ float t[32][33];
    const int n0 = blockIdx.x * 32, k0 = blockIdx.y * 32;
    const int tx = threadIdx.x, ty = threadIdx.y;
#pragma unroll
    for (int d = 0; d < 32; d += 8)
        t[ty + d][tx] = W[(size_t)(k0 + ty + d) * Ndim + n0 + tx];
    __syncthreads();
#pragma unroll
    for (int d = 0; d < 32; d += 8) {
        float v = t[tx][ty + d];
        __nv_bfloat16 h = __float2bfloat16(v);
        __nv_bfloat16 l = __float2bfloat16(v - __bfloat162float(h));
        size_t o = (size_t)(n0 + ty + d) * Kdim + k0 + tx;
        hiT[o] = h;
        loT[o] = l;
    }
}

// ---------------------------------------------------------------------------
// Row-gathered split: row i <- X[map[i], :]
// ---------------------------------------------------------------------------
__global__ __launch_bounds__(192) void conv_split_gather(
    const float* __restrict__ X, const int* __restrict__ map,
    __nv_bfloat16* __restrict__ hi, __nv_bfloat16* __restrict__ lo)
{
    const int row = blockIdx.x;
    const int src = map[row];
    const float4* xs = (const float4*)(X + (size_t)src * C_DIM);
    const int j = threadIdx.x;   // 192 threads, C_DIM/4 = 192
    float4 v = xs[j];
    __nv_bfloat16 h0 = __float2bfloat16(v.x), h1 = __float2bfloat16(v.y);
    __nv_bfloat16 h2 = __float2bfloat16(v.z), h3 = __float2bfloat16(v.w);
    __nv_bfloat16 l0 = __float2bfloat16(v.x - __bfloat162float(h0));
    __nv_bfloat16 l1 = __float2bfloat16(v.y - __bfloat162float(h1));
    __nv_bfloat16 l2 = __float2bfloat16(v.z - __bfloat162float(h2));
    __nv_bfloat16 l3 = __float2bfloat16(v.w - __bfloat162float(h3));
    __nv_bfloat162 hp0 = {h0, h1}, hp1 = {h2, h3};
    __nv_bfloat162 lp0 = {l0, l1}, lp1 = {l2, l3};
    uint2 hv, lv;
    hv.x = *(unsigned*)&hp0; hv.y = *(unsigned*)&hp1;
    lv.x = *(unsigned*)&lp0; lv.y = *(unsigned*)&lp1;
    ((uint2*)(hi + (size_t)row * C_DIM))[j] = hv;
    ((uint2*)(lo + (size_t)row * C_DIM))[j] = lv;
}

// ---------------------------------------------------------------------------
// HMMA split-bf16 GEMM: C[M,N] = A@B^T + bias.  A=[M,K] hi/lo, B=[N,K] hi/lo.
// CTA tile 128x128, BK=32, 8 warps (4M x 2N), warp tile 32x64, m16n8k16.
// 2-stage cp.async pipeline. smem rows padded to 80B for conflict-free ldmatrix.
// ---------------------------------------------------------------------------
#define TS        80                       // smem row stride bytes (32 bf16 + pad)
#define TILE_SZ   (128 * TS)               // 10240
#define OFF_AH    0
#define OFF_AL    TILE_SZ
#define OFF_BH    (2 * TILE_SZ)
#define OFF_BL    (3 * TILE_SZ)
#define STAGE_SZ  (4 * TILE_SZ)            // 40960
#define SMEM_GEMM (2 * STAGE_SZ)           // 81920

__global__ __launch_bounds__(256) void mma_gemm(
    const __nv_bfloat16* __restrict__ Ah, const __nv_bfloat16* __restrict__ Al,
    const __nv_bfloat16* __restrict__ Bh, const __nv_bfloat16* __restrict__ Bl,
    const float* __restrict__ bias, float* __restrict__ C, int Kdim, int Ndim)
{
    extern __shared__ char smem[];
    const unsigned sbase = smem_u32(smem);
    const int tid  = threadIdx.x;
    const int lane = tid & 31;
    const int wid  = tid >> 5;
    const int wm   = wid & 3;        // 0..3 -> M offset wm*32
    const int wn   = wid >> 2;       // 0..1 -> N offset wn*64
    const int bx = blockIdx.x, by = blockIdx.y;

    // gmem load mapping: per array, thread handles idx = tid, tid+256
    // idx -> row = idx/4, c16 = idx%4 (16B chunks of a 64B row)
    const int r0 = tid >> 2, c0 = (tid & 3);

    // ldmatrix lane address components
    const unsigned a_lane = (lane & 15) * TS + (lane >> 4) * 16;
    const unsigned b_lane = ((lane & 7) + ((lane >> 4) & 1) * 8) * TS +
                            ((lane >> 3) & 1) * 16;

    float acc[2][8][4];
#pragma unroll
    for (int mi = 0; mi < 2; mi++)
#pragma unroll
        for (int ni = 0; ni < 8; ni++)
#pragma unroll
            for (int c = 0; c < 4; c++) acc[mi][ni][c] = 0.0f;

    const int nch = Kdim >> 5;   // K chunks of 32

    // ---- stage loader (cp.async) ----
    auto load_stage = [&](int ch, int stage) {
        const int kt = ch << 5;
        const unsigned sb = sbase + stage * STAGE_SZ;
#pragma unroll
        for (int i = 0; i < 2; i++) {
            const int row = r0 + i * 64;
            const int c16 = c0;
            const unsigned so = row * TS + c16 * 16;
            const size_t ga = (size_t)(by * 128 + row) * Kdim + kt + c16 * 8;
            const size_t gb = (size_t)(bx * 128 + row) * Kdim + kt + c16 * 8;
            cp16(sb + OFF_AH + so, Ah + ga);
            cp16(sb + OFF_AL + so, Al + ga);
            cp16(sb + OFF_BH + so, Bh + gb);
            cp16(sb + OFF_BL + so, Bl + gb);
        }
        CP_COMMIT();
    };

    load_stage(0, 0);

    for (int ch = 0; ch < nch; ch++) {
        if (ch + 1 < nch) {
            load_stage(ch + 1, (ch + 1) & 1);
            CP_WAIT(1);
        } else {
            CP_WAIT(0);
        }
        __syncthreads();

        const unsigned sb = sbase + (ch & 1) * STAGE_SZ;
        const unsigned aH = sb + OFF_AH + (wm * 32) * TS + a_lane;
        const unsigned aL = sb + OFF_AL + (wm * 32) * TS + a_lane;
        const unsigned bH = sb + OFF_BH + (wn * 64) * TS + b_lane;
        const unsigned bL = sb + OFF_BL + (wn * 64) * TS + b_lane;

#pragma unroll
        for (int ks = 0; ks < 2; ks++) {
            unsigned ah[2][4], al[2][4], bh[4][4], bl[4][4];
#pragma unroll
            for (int mi = 0; mi < 2; mi++) {
                ldsm4(ah[mi], aH + mi * (16 * TS) + ks * 32);
                ldsm4(al[mi], aL + mi * (16 * TS) + ks * 32);
            }
#pragma unroll
            for (int nj = 0; nj < 4; nj++) {
                ldsm4(bh[nj], bH + nj * (16 * TS) + ks * 32);
                ldsm4(bl[nj], bL + nj * (16 * TS) + ks * 32);
            }
#pragma unroll
            for (int mi = 0; mi < 2; mi++)
#pragma unroll
                for (int nj = 0; nj < 4; nj++)
#pragma unroll
                    for (int hf = 0; hf < 2; hf++) {
                        const int ni = nj * 2 + hf;
                        mma_bf16(acc[mi][ni], ah[mi], &bh[nj][hf * 2]);  // h*h
                        mma_bf16(acc[mi][ni], ah[mi], &bl[nj][hf * 2]);  // h*l
                        mma_bf16(acc[mi][ni], al[mi], &bh[nj][hf * 2]);  // l*h
                    }
        }
        __syncthreads();
    }

    // ---- epilogue: bias + store fp32 ----
#pragma unroll
    for (int ni = 0; ni < 8; ni++) {
        const int col = bx * 128 + wn * 64 + ni * 8 + (lane & 3) * 2;
        const float2 bb = *(const float2*)(bias + col);
#pragma unroll
        for (int mi = 0; mi < 2; mi++) {
            const int row = by * 128 + wm * 32 + mi * 16 + (lane >> 2);
            float2 v0, v1;
            v0.x = acc[mi][ni][0] + bb.x;
            v0.y = acc[mi][ni][1] + bb.y;
            v1.x = acc[mi][ni][2] + bb.x;
            v1.y = acc[mi][ni][3] + bb.y;
            *(float2*)(C + (size_t)row * Ndim + col) = v0;
            *(float2*)(C + (size_t)(row + 8) * Ndim + col) = v1;
        }
    }
}

// ---------------------------------------------------------------------------
// Gather by `order` + 3-axis RoPE on q,k; straight copy for v.  (fp32)
// ---------------------------------------------------------------------------
__global__ __launch_bounds__(384) void gather_rope_kernel(
    const int* __restrict__ order, const int* __restrict__ grid_coord)
{
    const int n = blockIdx.x;
    const int tid = threadIdx.x;
    const int src = order[n];

    const float* qkv = g_qkv + (size_t)src * NQKV;
    float* qo = g_q + (size_t)n * C_DIM;
    float* ko = g_k + (size_t)n * C_DIM;
    float* vo = g_v + (size_t)n * C_DIM;

    for (int j = tid; j < C_DIM; j += 384)
        vo[j] = qkv[2 * C_DIM + j];

    const int h = tid / 48;
    const int rem = tid % 48;
    const int a = rem / 16;
    const int i = rem & 15;

    const float pos = (float)grid_coord[src * 3 + a];
    const float invf = exp2f(-(float)i * 0.4152410118609212f);
    const float ang = pos * invf;
    float s, c;
    sincosf(ang, &s, &c);

    const int base = h * 96 + a * 32 + i;
    {
        float x1 = qkv[base];
        float x2 = qkv[base + 16];
        qo[base]      = x1 * c - x2 * s;
        qo[base + 16] = x1 * s + x2 * c;
    }
    {
        float x1 = qkv[C_DIM + base];
        float x2 = qkv[C_DIM + base + 16];
        ko[base]      = x1 * c - x2 * s;
        ko[base + 16] = x1 * s + x2 * c;
    }
}

// ---------------------------------------------------------------------------
// Packed fp32x2 helpers for attention
// ---------------------------------------------------------------------------
__device__ __forceinline__ unsigned long long dup2(float x) {
    unsigned long long r;
    asm("mov.b64 %0, {%1, %1};" : "=l"(r) : "f"(x));
    return r;
}
__device__ __forceinline__ void fma2(unsigned long long& d,
                                     unsigned long long a, unsigned long long b) {
    asm("fma.rn.f32x2 %0, %1, %2, %0;" : "+l"(d) : "l"(a), "l"(b));
}
__device__ __forceinline__ unsigned long long mul2(unsigned long long a,
                                                   unsigned long long b) {
    unsigned long long r;
    asm("mul.rn.f32x2 %0, %1, %2;" : "=l"(r) : "l"(a), "l"(b));
    return r;
}
__device__ __forceinline__ float2 unpk2(unsigned long long v) {
    float2 f;
    asm("mov.b64 {%0, %1}, %2;" : "=f"(f.x), "=f"(f.y) : "l"(v));
    return f;
}

// ---------------------------------------------------------------------------
// Windowed attention: block per (window, head), 256 threads = 1 query/thread.
// ---------------------------------------------------------------------------
__global__ __launch_bounds__(256, 1) void attn_kernel()
{
    extern __shared__ float sm[];
    float* ks = sm;
    float* vs = sm + K_WIN * HD_DIM;

    const int p = blockIdx.x;
    const int h = blockIdx.y;
    const int tid = threadIdx.x;

    const float* kbase = g_k + (size_t)p * K_WIN * C_DIM + h * HD_DIM;
    const float* vbase = g_v + (size_t)p * K_WIN * C_DIM + h * HD_DIM;

    for (int idx = tid; idx < K_WIN * (HD_DIM / 4); idx += 256) {
        const int j  = idx / (HD_DIM / 4);
        const int c4 = idx % (HD_DIM / 4);
        ((float4*)ks)[idx] = *(const float4*)(kbase + (size_t)j * C_DIM + c4 * 4);
        ((float4*)vs)[idx] = *(const float4*)(vbase + (size_t)j * C_DIM + c4 * 4);
    }

    unsigned long long q2[HD_DIM / 2];
    {
        const double2* qrow = (const double2*)(g_q + (size_t)(p * K_WIN + tid) * C_DIM + h * HD_DIM);
#pragma unroll
        for (int c = 0; c < HD_DIM / 4; c++) {
            double2 t = qrow[c];
            q2[2 * c + 0] = __double_as_longlong(t.x);
            q2[2 * c + 1] = __double_as_longlong(t.y);
        }
    }
    __syncthreads();

    const float scale = rsqrtf((float)HD_DIM);

    float m = -1e30f;
    float l = 0.0f;
    unsigned long long o2[HD_DIM / 2];
#pragma unroll
    for (int c = 0; c < HD_DIM / 2; c++) o2[c] = 0ull;

    for (int j = 0; j < K_WIN; j++) {
        const double2* kr = (const double2*)(ks + j * HD_DIM);
        unsigned long long acc[4] = {0ull, 0ull, 0ull, 0ull};
#pragma unroll
        for (int c = 0; c < HD_DIM / 4; c++) {
            double2 t = kr[c];
            fma2(acc[(2 * c) & 3],     q2[2 * c + 0], __double_as_longlong(t.x));
            fma2(acc[(2 * c + 1) & 3], q2[2 * c + 1], __double_as_longlong(t.y));
        }
        float2 r0 = unpk2(acc[0]), r1 = unpk2(acc[1]);
        float2 r2 = unpk2(acc[2]), r3 = unpk2(acc[3]);
        float dot = ((r0.x + r0.y) + (r1.x + r1.y)) + ((r2.x + r2.y) + (r3.x + r3.y));

        float pnum;
        if (dot > m) {
            float corr = __expf((m - dot) * scale);
            unsigned long long corr2 = dup2(corr);
#pragma unroll
            for (int c = 0; c < HD_DIM / 2; c++) o2[c] = mul2(o2[c], corr2);
            l *= corr;
            m = dot;
            pnum = 1.0f;
        } else {
            pnum = __expf((dot - m) * scale);
        }
        l += pnum;

        unsigned long long p2 = dup2(pnum);
        const double2* vr = (const double2*)(vs + j * HD_DIM);
#pragma unroll
        for (int c = 0; c < HD_DIM / 4; c++) {
            double2 t = vr[c];
            fma2(o2[2 * c + 0], p2, __double_as_longlong(t.x));
            fma2(o2[2 * c + 1], p2, __double_as_longlong(t.y));
        }
    }

    const float invl = 1.0f / l;
    float* orow = g_att + (size_t)(p * K_WIN + tid) * C_DIM + h * HD_DIM;
#pragma unroll
    for (int c = 0; c < HD_DIM / 4; c++) {
        float2 a = unpk2(o2[2 * c + 0]);
        float2 b = unpk2(o2[2 * c + 1]);
        float4 ov;
        ov.x = a.x * invl;
        ov.y = a.y * invl;
        ov.z = b.x * invl;
        ov.w = b.y * invl;
        *(float4*)(orow + c * 4) = ov;
    }
}

// ---------------------------------------------------------------------------
// Launch
// ---------------------------------------------------------------------------
extern "C" void kernel_launch(void* const* d_in, const int* in_sizes, int n_in,
                              void* d_out, int out_size)
{
    const float* feat       = (const float*)d_in[0];
    const int*   grid_coord = (const int*)d_in[1];
    const int*   order      = (const int*)d_in[2];
    const int*   inverse    = (const int*)d_in[3];
    const float* w_qkv      = (const float*)d_in[4];
    const float* b_qkv      = (const float*)d_in[5];
    const float* w_proj     = (const float*)d_in[6];
    const float* b_proj     = (const float*)d_in[7];
    float* out = (float*)d_out;

    float *qkv_p = nullptr, *att_p = nullptr;
    cudaGetSymbolAddress((void**)&qkv_p, g_qkv);
    cudaGetSymbolAddress((void**)&att_p, g_att);

    __nv_bfloat16 *Ah, *Al, *A2h, *A2l, *Bqh, *Bql, *Bph, *Bpl;
    cudaGetSymbolAddress((void**)&Ah,  g_Ah);
    cudaGetSymbolAddress((void**)&Al,  g_Al);
    cudaGetSymbolAddress((void**)&A2h, g_A2h);
    cudaGetSymbolAddress((void**)&A2l, g_A2l);
    cudaGetSymbolAddress((void**)&Bqh, g_Bqh);
    cudaGetSymbolAddress((void**)&Bql, g_Bql);
    cudaGetSymbolAddress((void**)&Bph, g_Bph);
    cudaGetSymbolAddress((void**)&Bpl, g_Bpl);

    const int smem_attn = K_WIN * HD_DIM * 2 * sizeof(float);  // 196608 B
    cudaFuncSetAttribute(attn_kernel, cudaFuncAttributeMaxDynamicSharedMemorySize, smem_attn);
    cudaFuncSetAttribute(mma_gemm, cudaFuncAttributeMaxDynamicSharedMemorySize, SMEM_GEMM);

    // 0) operand conversions
    {
        int n4 = N_TOK * C_DIM / 4;
        conv_split<<<(n4 + 255) / 256, 256>>>(feat, Ah, Al, n4);
        conv_split_T<<<dim3(NQKV / 32, C_DIM / 32), dim3(32, 8)>>>(w_qkv, Bqh, Bql, C_DIM, NQKV);
        conv_split_T<<<dim3(C_DIM / 32, C_DIM / 32), dim3(32, 8)>>>(w_proj, Bph, Bpl, C_DIM, C_DIM);
    }

    // 1) qkv = feat @ w_qkv + b_qkv  (HMMA, split bf16)
    mma_gemm<<<dim3(NQKV / 128, N_TOK / 128), 256, SMEM_GEMM>>>(
        Ah, Al, Bqh, Bql, b_qkv, qkv_p, C_DIM, NQKV);

    // 2) gather by order + RoPE
    gather_rope_kernel<<<N_TOK, 384>>>(order, grid_coord);

    // 3) windowed attention
    attn_kernel<<<dim3(P_WIN, H_HEADS), 256, smem_attn>>>();

    // 4) gathered conversion of attention output (fuses `inverse` permute)
    conv_split_gather<<<N_TOK, 192>>>(att_p, inverse, A2h, A2l);

    // 5) out = g_att[inverse] @ w_proj + b_proj
    mma_gemm<<<dim3(C_DIM / 128, N_TOK / 128), 256, SMEM_GEMM>>>(
        A2h, A2l, Bph, Bpl, b_proj, out, C_DIM, C_DIM);
}